// round 11
// baseline (speedup 1.0000x reference)
#include <cuda_runtime.h>
#include <cuda_bf16.h>

// Problem constants (fixed by the reference).
#define B_   16
#define S_   1024
#define H_   256
#define TOUT 4096          // S * D_MAX
#define NBIN 256
#define ROWS (B_ * TOUT)
#define PADW 2048          // padding-writer warps

// Scratch (device globals: no allocation allowed).
__device__ int   g_sd[B_ * S_];    // per-phoneme: (start << 3) | d
__device__ int   g_len[B_];        // per-batch expanded length
__device__ uint2 g_pt16[NBIN * 64];  // pitch table, bf16 (256 rows x 256 cols)
__device__ uint2 g_et16[NBIN * 64];  // energy table, bf16

// ---------------------------------------------------------------------------
// Kernel 1: per-batch inclusive cumsum of rounded durations -> (start,d) per
// phoneme + lengths; ALSO converts both embedding tables to bf16 (each of the
// 16384 threads converts 4 elements of each table).
// Grid: B_ blocks of S_ threads.
// ---------------------------------------------------------------------------
__global__ void scan_prep_kernel(const float* __restrict__ dur,
                                 const float4* __restrict__ ptab,
                                 const float4* __restrict__ etab,
                                 float* __restrict__ out,
                                 long long out_size) {
    const int b = blockIdx.x;
    const int i = threadIdx.x;

    int d = (int)rintf(dur[b * S_ + i]);
    d = max(d, 0);

    const int lane = i & 31, warp = i >> 5;
    int v = d;
#pragma unroll
    for (int o = 1; o < 32; o <<= 1) {
        int n = __shfl_up_sync(0xffffffffu, v, o);
        if (lane >= o) v += n;
    }
    __shared__ int wsum[32];
    if (lane == 31) wsum[warp] = v;
    __syncthreads();
    if (warp == 0) {
        int w = wsum[lane];
#pragma unroll
        for (int o = 1; o < 32; o <<= 1) {
            int n = __shfl_up_sync(0xffffffffu, w, o);
            if (lane >= o) w += n;
        }
        wsum[lane] = w;
    }
    __syncthreads();
    const int csum  = v + (warp > 0 ? wsum[warp - 1] : 0);  // inclusive
    const int start = csum - d;

    g_sd[b * S_ + i] = (start << 3) | d;

    if (i == S_ - 1) {
        g_len[b] = csum;
        if (out_size >= (long long)ROWS * H_ + B_)
            out[out_size - B_ + b] = (float)csum;   // lengths at tuple tail
    }

    // Table conversion: global tid in [0, 16384); each handles 4 f32 -> 4 bf16
    // of each table (65536 elements per table / 4 = 16384).
    const int tid = b * S_ + i;
    {
        const float4 pf = __ldg(ptab + tid);
        const float4 ef = __ldg(etab + tid);
        uint2 pu, eu;
        __nv_bfloat162 t;
        t = __float22bfloat162_rn(make_float2(pf.x, pf.y)); pu.x = *(unsigned*)&t;
        t = __float22bfloat162_rn(make_float2(pf.z, pf.w)); pu.y = *(unsigned*)&t;
        t = __float22bfloat162_rn(make_float2(ef.x, ef.y)); eu.x = *(unsigned*)&t;
        t = __float22bfloat162_rn(make_float2(ef.z, ef.w)); eu.y = *(unsigned*)&t;
        g_pt16[tid] = pu;
        g_et16[tid] = eu;
    }
}

// ---------------------------------------------------------------------------
// Quantize: jnp.searchsorted(linspace(vmin,vmax,256), clip(v), 'left'),
// clipped to [0,255]. Closed-form ceil with +-1 fixup vs exact boundaries.
// ---------------------------------------------------------------------------
__device__ __forceinline__ int qbin(float v, float vmin, float vmax,
                                    float invstep, float step) {
    v = fminf(fmaxf(v, vmin), vmax);
    int k = (int)ceilf((v - vmin) * invstep);
    k = min(max(k, 0), NBIN - 1);
    if (k > 0 && (vmin + (float)(k - 1) * step) >= v) k--;
    else if ((vmin + (float)k * step) < v) k = min(k + 1, NBIN - 1);
    return k;
}

// a (f32x4) + bf16x4 + bf16x4
__device__ __forceinline__ float4 add3(float4 a, uint2 p, uint2 e) {
    const float2 p01 = __bfloat1622float2(*(const __nv_bfloat162*)&p.x);
    const float2 p23 = __bfloat1622float2(*(const __nv_bfloat162*)&p.y);
    const float2 e01 = __bfloat1622float2(*(const __nv_bfloat162*)&e.x);
    const float2 e23 = __bfloat1622float2(*(const __nv_bfloat162*)&e.y);
    return make_float4(a.x + p01.x + e01.x,
                       a.y + p01.y + e01.y,
                       a.z + p23.x + e23.x,
                       a.w + p23.y + e23.y);
}

// ---------------------------------------------------------------------------
// Kernel 2: warp-per-phoneme expansion. Each of the 16384 phoneme-warps loads
// its encoder row ONCE (f32) and writes its d (1..4) output frames, adding the
// bf16 pitch/energy embeddings gathered per frame. Table traffic halves (bf16)
// and enc traffic drops ~2.5x (one read per phoneme instead of per frame).
// Warps [16384, 16384+PADW) zero the padding rows (store-only).
// ---------------------------------------------------------------------------
__global__ void __launch_bounds__(256, 6)
expand_ph_kernel(const float4* __restrict__ enc,
                 const float*  __restrict__ pitch_t,
                 const float*  __restrict__ energy_t,
                 float4*       __restrict__ out) {
    const int W    = (blockIdx.x * blockDim.x + threadIdx.x) >> 5;
    const int lane = threadIdx.x & 31;

    if (W < B_ * S_) {
        // ---- phoneme path ----
        const int sd    = g_sd[W];
        const int d     = sd & 7;
        if (d == 0) return;
        const int start = sd >> 3;
        const int b     = W >> 10;               // / S_

        const float4* __restrict__ er = enc + (size_t)W * (H_ / 4);
        const float4 a0 = er[lane];
        const float4 a1 = er[lane + 32];

        int row = (b << 12) + start;
#pragma unroll 4
        for (int k = 0; k < 4; ++k, ++row) {
            if (k >= d) break;
            const float pv = __ldg(pitch_t + row);
            const float ev = __ldg(energy_t + row);
            const int pb = qbin(pv, 50.0f, 400.0f, 255.0f / 350.0f, 350.0f / 255.0f);
            const int eb = qbin(ev,  0.0f,   1.0f, 255.0f,          1.0f / 255.0f);

            const uint2 p0 = g_pt16[pb * 64 + lane];
            const uint2 p1 = g_pt16[pb * 64 + lane + 32];
            const uint2 e0 = g_et16[eb * 64 + lane];
            const uint2 e1 = g_et16[eb * 64 + lane + 32];

            const size_t rowo = (size_t)row * (H_ / 4);
            out[rowo + lane]      = add3(a0, p0, e0);
            out[rowo + lane + 32] = add3(a1, p1, e1);
        }
    } else {
        // ---- padding path: zero rows j >= len[b] ----
        const int t = W - B_ * S_;               // 0..PADW-1
        const float4 z = make_float4(0.f, 0.f, 0.f, 0.f);
        for (int row = t; row < ROWS; row += PADW) {
            const int b = row >> 12;
            const int j = row & (TOUT - 1);
            if (j >= g_len[b]) {
                const size_t rowo = (size_t)row * (H_ / 4);
                out[rowo + lane]      = z;
                out[rowo + lane + 32] = z;
            }
        }
    }
}

extern "C" void kernel_launch(void* const* d_in, const int* in_sizes, int n_in,
                              void* d_out, int out_size) {
    const float* enc      = (const float*)d_in[0];   // [B,S,H]
    const float* pitch_t  = (const float*)d_in[1];   // [B,TOUT]
    const float* energy_t = (const float*)d_in[2];   // [B,TOUT]
    const float* dur      = (const float*)d_in[3];   // [B,S]
    const float* ptab     = (const float*)d_in[4];   // [256,H]
    const float* etab     = (const float*)d_in[5];   // [256,H]
    float* out            = (float*)d_out;

    scan_prep_kernel<<<B_, S_>>>(dur, (const float4*)ptab, (const float4*)etab,
                                 out, (long long)out_size);

    // 16384 phoneme warps + PADW padding warps, 8 warps per block.
    const int warps  = B_ * S_ + PADW;       // 18432
    const int blocks = warps / 8;            // 2304
    expand_ph_kernel<<<blocks, 256>>>((const float4*)enc, pitch_t, energy_t,
                                      (float4*)out);
}

// round 15
// speedup vs baseline: 1.2871x; 1.2871x over previous
#include <cuda_runtime.h>
#include <cuda_bf16.h>

// Problem constants (fixed by the reference).
#define B_   16
#define S_   1024
#define H_   256
#define TOUT 4096          // S * D_MAX
#define NBIN 256
#define ROWS (B_ * TOUT)

// Scratch (device globals: no allocation allowed).
__device__ int   g_src[ROWS];        // frame -> phoneme index (valid j < len)
__device__ int   g_len[B_];          // per-batch expanded length
__device__ uint2 g_pt16[NBIN * 64];  // pitch table bf16: row=bin, 64 uint2 = 256 vals
__device__ uint2 g_et16[NBIN * 64];  // energy table bf16

// ---------------------------------------------------------------------------
// Kernel 1: per-batch inclusive cumsum of rounded durations, scatter the
// frame->phoneme map, emit lengths; ALSO converts both embedding tables to
// bf16 (each of the 16384 threads converts 4 elements of each table).
// Grid: B_ blocks of S_ threads.
// ---------------------------------------------------------------------------
__global__ void scan_prep_kernel(const float* __restrict__ dur,
                                 const float4* __restrict__ ptab,
                                 const float4* __restrict__ etab,
                                 float* __restrict__ out,
                                 long long out_size) {
    const int b = blockIdx.x;
    const int i = threadIdx.x;

    int d = (int)rintf(dur[b * S_ + i]);
    d = max(d, 0);

    const int lane = i & 31, warp = i >> 5;
    int v = d;
#pragma unroll
    for (int o = 1; o < 32; o <<= 1) {
        int n = __shfl_up_sync(0xffffffffu, v, o);
        if (lane >= o) v += n;
    }
    __shared__ int wsum[32];
    if (lane == 31) wsum[warp] = v;
    __syncthreads();
    if (warp == 0) {
        int w = wsum[lane];
#pragma unroll
        for (int o = 1; o < 32; o <<= 1) {
            int n = __shfl_up_sync(0xffffffffu, w, o);
            if (lane >= o) w += n;
        }
        wsum[lane] = w;
    }
    __syncthreads();
    const int csum  = v + (warp > 0 ? wsum[warp - 1] : 0);  // inclusive
    const int start = csum - d;

    for (int j = start; j < csum; ++j)
        g_src[b * TOUT + j] = i;

    if (i == S_ - 1) {
        g_len[b] = csum;
        if (out_size >= (long long)ROWS * H_ + B_)
            out[out_size - B_ + b] = (float)csum;   // lengths at tuple tail
    }

    // Table conversion: 16384 global threads x 4 f32 elements per table.
    const int tid = b * S_ + i;
    {
        const float4 pf = __ldg(ptab + tid);
        const float4 ef = __ldg(etab + tid);
        uint2 pu, eu;
        __nv_bfloat162 t;
        t = __float22bfloat162_rn(make_float2(pf.x, pf.y)); pu.x = *(unsigned*)&t;
        t = __float22bfloat162_rn(make_float2(pf.z, pf.w)); pu.y = *(unsigned*)&t;
        t = __float22bfloat162_rn(make_float2(ef.x, ef.y)); eu.x = *(unsigned*)&t;
        t = __float22bfloat162_rn(make_float2(ef.z, ef.w)); eu.y = *(unsigned*)&t;
        g_pt16[tid] = pu;
        g_et16[tid] = eu;
    }
}

// ---------------------------------------------------------------------------
// Quantize: jnp.searchsorted(linspace(vmin,vmax,256), clip(v), 'left'),
// clipped to [0,255]. Closed-form ceil with +-1 fixup vs exact boundaries.
// ---------------------------------------------------------------------------
__device__ __forceinline__ int qbin(float v, float vmin, float vmax,
                                    float invstep, float step) {
    v = fminf(fmaxf(v, vmin), vmax);
    int k = (int)ceilf((v - vmin) * invstep);
    k = min(max(k, 0), NBIN - 1);
    if (k > 0 && (vmin + (float)(k - 1) * step) >= v) k--;
    else if ((vmin + (float)k * step) < v) k = min(k + 1, NBIN - 1);
    return k;
}

// f32x4 + bf16x4 + bf16x4
__device__ __forceinline__ float4 add3(float4 a, uint2 p, uint2 e) {
    const float2 p01 = __bfloat1622float2(*(const __nv_bfloat162*)&p.x);
    const float2 p23 = __bfloat1622float2(*(const __nv_bfloat162*)&p.y);
    const float2 e01 = __bfloat1622float2(*(const __nv_bfloat162*)&e.x);
    const float2 e23 = __bfloat1622float2(*(const __nv_bfloat162*)&e.y);
    return make_float4(a.x + p01.x + e01.x,
                       a.y + p01.y + e01.y,
                       a.z + p23.x + e23.x,
                       a.w + p23.y + e23.y);
}

// ---------------------------------------------------------------------------
// Kernel 2: one warp per output row (R1/R8 geometry — best measured), but the
// table gathers are bf16 (uint2 per lane-chunk): per-row L1 wavefronts drop
// from 33 to 25.
// ---------------------------------------------------------------------------
__global__ void __launch_bounds__(256, 6)
expand_kernel(const float4* __restrict__ enc,
              const float*  __restrict__ pitch_t,
              const float*  __restrict__ energy_t,
              float4*       __restrict__ out) {
    const int w    = (blockIdx.x * blockDim.x + threadIdx.x) >> 5;  // row id
    const int lane = threadIdx.x & 31;

    const int b = w >> 12;          // / TOUT
    const int j = w & (TOUT - 1);

    const size_t rowo = (size_t)w * (H_ / 4);

    if (j >= g_len[b]) {
        const float4 z = make_float4(0.f, 0.f, 0.f, 0.f);
        out[rowo + lane]      = z;
        out[rowo + lane + 32] = z;
        return;
    }

    const int src = g_src[w];
    const float pv = __ldg(pitch_t + w);
    const float ev = __ldg(energy_t + w);
    const int pb = qbin(pv, 50.0f, 400.0f, 255.0f / 350.0f, 350.0f / 255.0f);
    const int eb = qbin(ev,  0.0f,   1.0f, 255.0f,          1.0f / 255.0f);

    const float4* __restrict__ er = enc + ((size_t)(b * S_ + src)) * (H_ / 4);

    const float4 a0 = er[lane];
    const float4 a1 = er[lane + 32];
    const uint2  p0 = g_pt16[pb * 64 + lane];
    const uint2  p1 = g_pt16[pb * 64 + lane + 32];
    const uint2  e0 = g_et16[eb * 64 + lane];
    const uint2  e1 = g_et16[eb * 64 + lane + 32];

    out[rowo + lane]      = add3(a0, p0, e0);
    out[rowo + lane + 32] = add3(a1, p1, e1);
}

extern "C" void kernel_launch(void* const* d_in, const int* in_sizes, int n_in,
                              void* d_out, int out_size) {
    const float* enc      = (const float*)d_in[0];   // [B,S,H]
    const float* pitch_t  = (const float*)d_in[1];   // [B,TOUT]
    const float* energy_t = (const float*)d_in[2];   // [B,TOUT]
    const float* dur      = (const float*)d_in[3];   // [B,S]
    const float* ptab     = (const float*)d_in[4];   // [256,H]
    const float* etab     = (const float*)d_in[5];   // [256,H]
    float* out            = (float*)d_out;

    scan_prep_kernel<<<B_, S_>>>(dur, (const float4*)ptab, (const float4*)etab,
                                 out, (long long)out_size);

    const int rows   = ROWS;             // 65536 warps
    const int blocks = rows / 8;         // 8 warps (rows) per 256-thread block
    expand_kernel<<<blocks, 256>>>((const float4*)enc, pitch_t, energy_t,
                                   (float4*)out);
}